// round 3
// baseline (speedup 1.0000x reference)
#include <cuda_runtime.h>
#include <cuda_fp16.h>
#include <cstdint>

#define OUTF 4096
#define INF  4096
#define MDIM 1024

// fp16 scratch — static device globals (allocation-free)
__device__ __half g_wh[(size_t)OUTF * INF];   // dequantized W [out, in]
__device__ __half g_xh[(size_t)MDIM * INF];   // x fp16 [m, k]

// ---------------------------------------------------------------------------
// helpers
// ---------------------------------------------------------------------------
__device__ __forceinline__ uint32_t smem_u32(const void* p) {
    uint32_t a;
    asm("{ .reg .u64 t; cvta.to.shared.u64 t, %1; cvt.u32.u64 %0, t; }"
        : "=r"(a) : "l"(p));
    return a;
}

__device__ __forceinline__ void cp16(uint32_t saddr, const void* gaddr) {
    asm volatile("cp.async.cg.shared.global [%0], [%1], 16;"
                 :: "r"(saddr), "l"(gaddr) : "memory");
}

// ---------------------------------------------------------------------------
// Kernel 1: x fp32 -> fp16
// ---------------------------------------------------------------------------
__global__ void convert_x_kernel(const float4* __restrict__ x) {
    int i = blockIdx.x * blockDim.x + threadIdx.x;
    float4 v = x[i];
    __half2 a = __floats2half2_rn(v.x, v.y);
    __half2 b = __floats2half2_rn(v.z, v.w);
    uint2 u;
    u.x = *reinterpret_cast<uint32_t*>(&a);
    u.y = *reinterpret_cast<uint32_t*>(&b);
    reinterpret_cast<uint2*>(g_xh)[i] = u;
}

// ---------------------------------------------------------------------------
// Kernel 2: int4 dequant -> fp16   ((q - zero) * scale)
// ---------------------------------------------------------------------------
__global__ void dequant_w_kernel(const int* __restrict__ wp,
                                 const float* __restrict__ ws,
                                 const int* __restrict__ wz) {
    int p = blockIdx.x * blockDim.x + threadIdx.x;   // one packed int32
    int v = wp[p];
    int o    = p >> 9;         // 512 packed ints per output row
    int col8 = p & 511;        // packed column within row
    int g    = col8 >> 4;      // group index: (col8*8)/128
    float s = ws[o * 32 + g];
    float z = (float)wz[o * 32 + g];
    uint32_t pk[4];
#pragma unroll
    for (int jj = 0; jj < 4; ++jj) {
        int q0 = (v >> (8 * jj)) & 15;
        int q1 = (v >> (8 * jj + 4)) & 15;
        q0 = (q0 ^ 8) - 8;   // signed 4-bit
        q1 = (q1 ^ 8) - 8;
        __half2 h = __floats2half2_rn(((float)q0 - z) * s, ((float)q1 - z) * s);
        pk[jj] = *reinterpret_cast<uint32_t*>(&h);
    }
    *reinterpret_cast<uint4*>(&g_wh[(size_t)o * INF + col8 * 8]) =
        make_uint4(pk[0], pk[1], pk[2], pk[3]);
}

// ---------------------------------------------------------------------------
// Kernel 3: mma.sync fp16 GEMM — CTA 128x128, BK=64 halves, 3-stage cp.async
// 8 warps as 2(M) x 4(N); warp tile 64x32; mma.m16n8k16, fp32 accum.
// ---------------------------------------------------------------------------
constexpr int BM = 128, BN = 128, BK = 64;
constexpr int STAGES = 3;
constexpr int NIT = INF / BK;              // 64
constexpr int TILE = BM * 128;             // 16384 B per tile (128 rows x 128B)
constexpr int STG  = 2 * TILE;             // A + B per stage
constexpr int SMEM_BYTES = STAGES * STG;   // 98304

__global__ void __launch_bounds__(256, 1) gemm_kernel(float* __restrict__ out) {
    extern __shared__ char smem[];
    const uint32_t sb = smem_u32(smem);
    const int tid = threadIdx.x;
    const int wid = tid >> 5;
    const int lid = tid & 31;
    const int wm = wid >> 2;               // 0..1
    const int wn = wid & 3;                // 0..3
    const int n0 = blockIdx.x * BN;
    const int m0 = blockIdx.y * BM;

    const char* gA = (const char*)g_xh + (size_t)m0 * (INF * 2);
    const char* gB = (const char*)g_wh + (size_t)n0 * (INF * 2);

    // cp.async pattern: 1024 16B-chunks per tile, 4 per thread per tile.
    uint32_t soff[4]; size_t goff[4];
#pragma unroll
    for (int r = 0; r < 4; ++r) {
        int idx = tid + r * 256;
        int row = idx >> 3;
        int cc  = idx & 7;
        soff[r] = (uint32_t)(row * 128 + ((cc ^ (row & 7)) << 4));   // SW128 xor
        goff[r] = (size_t)row * (INF * 2) + (size_t)cc * 16;
    }
    auto load_chunk = [&](int kc, int s) {
        uint32_t tb = sb + s * STG;
        size_t kb = (size_t)kc * 128;
#pragma unroll
        for (int r = 0; r < 4; ++r) cp16(tb + soff[r], gA + goff[r] + kb);
#pragma unroll
        for (int r = 0; r < 4; ++r) cp16(tb + TILE + soff[r], gB + goff[r] + kb);
        asm volatile("cp.async.commit_group;" ::: "memory");
    };

    // ldmatrix per-thread row/chunk assignment
    // A x4: lanes 0-15 -> rows m..m+15 (k-low 16B); lanes 16-31 -> same rows (k-high)
    const int a_row7 = wm * 64 + (lid & 15);   // + i*16 later
    const int a_cb   = lid >> 4;               // 0: k0-7, 1: k8-15
    // B x4: lanes 0-7: n..n+7 klow; 8-15: n..n+7 khigh; 16-23: n+8.. klow; 24-31: khigh
    const int b_lrow = (lid & 7) + ((lid >> 4) << 3);
    const int b_cb   = (lid >> 3) & 1;
    const int b_row0 = wn * 32 + b_lrow;       // + h*16 later

    float acc[4][4][4];
#pragma unroll
    for (int i = 0; i < 4; ++i)
#pragma unroll
        for (int j = 0; j < 4; ++j)
#pragma unroll
            for (int q = 0; q < 4; ++q) acc[i][j][q] = 0.f;

    load_chunk(0, 0);
    load_chunk(1, 1);
    asm volatile("cp.async.wait_group 1;" ::: "memory");
    __syncthreads();

    for (int it = 0; it < NIT; ++it) {
        const uint32_t tb = sb + (it % 3) * STG;
#pragma unroll
        for (int ks = 0; ks < 4; ++ks) {            // 4 x k16 per 64-half chunk
            uint32_t a[4][4];
#pragma unroll
            for (int i = 0; i < 4; ++i) {
                int row = a_row7 + i * 16;
                uint32_t ad = tb + row * 128
                            + ((((ks << 1) + a_cb) ^ (row & 7)) << 4);
                asm volatile(
                    "ldmatrix.sync.aligned.m8n8.x4.shared.b16 {%0,%1,%2,%3}, [%4];"
                    : "=r"(a[i][0]), "=r"(a[i][1]), "=r"(a[i][2]), "=r"(a[i][3])
                    : "r"(ad));
            }
            uint32_t b[4][2];
#pragma unroll
            for (int h = 0; h < 2; ++h) {
                int row = b_row0 + h * 16;
                uint32_t bd = tb + TILE + row * 128
                            + ((((ks << 1) + b_cb) ^ (row & 7)) << 4);
                uint32_t r0, r1, r2, r3;
                asm volatile(
                    "ldmatrix.sync.aligned.m8n8.x4.shared.b16 {%0,%1,%2,%3}, [%4];"
                    : "=r"(r0), "=r"(r1), "=r"(r2), "=r"(r3) : "r"(bd));
                b[2 * h][0] = r0; b[2 * h][1] = r1;
                b[2 * h + 1][0] = r2; b[2 * h + 1][1] = r3;
            }
#pragma unroll
            for (int i = 0; i < 4; ++i)
#pragma unroll
                for (int j = 0; j < 4; ++j)
                    asm volatile(
                        "mma.sync.aligned.m16n8k16.row.col.f32.f16.f16.f32 "
                        "{%0,%1,%2,%3},{%4,%5,%6,%7},{%8,%9},{%0,%1,%2,%3};"
                        : "+f"(acc[i][j][0]), "+f"(acc[i][j][1]),
                          "+f"(acc[i][j][2]), "+f"(acc[i][j][3])
                        : "r"(a[i][0]), "r"(a[i][1]), "r"(a[i][2]), "r"(a[i][3]),
                          "r"(b[j][0]), "r"(b[j][1]));
        }
        // stage (it+2)%3 == (it-1)%3: fully consumed + barriered at iter it-1.
        if (it + 2 < NIT) {
            load_chunk(it + 2, (it + 2) % 3);
            asm volatile("cp.async.wait_group 1;" ::: "memory");
        } else {
            asm volatile("cp.async.wait_group 0;" ::: "memory");
        }
        __syncthreads();
    }

    // epilogue: c0,c1 = (row l/4, col 2(l%4)); c2,c3 = row+8.
    const int mrow = m0 + wm * 64 + (lid >> 2);
    const int ncol = n0 + wn * 32 + ((lid & 3) << 1);
#pragma unroll
    for (int i = 0; i < 4; ++i) {
#pragma unroll
        for (int j = 0; j < 4; ++j) {
            float* p0 = out + (size_t)(mrow + i * 16) * OUTF + ncol + j * 8;
            float* p1 = out + (size_t)(mrow + i * 16 + 8) * OUTF + ncol + j * 8;
            *reinterpret_cast<float2*>(p0) = make_float2(acc[i][j][0], acc[i][j][1]);
            *reinterpret_cast<float2*>(p1) = make_float2(acc[i][j][2], acc[i][j][3]);
        }
    }
}

// ---------------------------------------------------------------------------
// launch
// ---------------------------------------------------------------------------
extern "C" void kernel_launch(void* const* d_in, const int* in_sizes, int n_in,
                              void* d_out, int out_size) {
    const float* x  = (const float*)d_in[0];
    const int*   wp = (const int*)d_in[1];
    const float* ws = (const float*)d_in[2];
    const int*   wz = (const int*)d_in[3];
    float* out = (float*)d_out;

    cudaFuncSetAttribute(gemm_kernel,
                         cudaFuncAttributeMaxDynamicSharedMemorySize, SMEM_BYTES);

    convert_x_kernel<<<(MDIM * INF / 4) / 256, 256>>>(
        reinterpret_cast<const float4*>(x));
    dequant_w_kernel<<<(OUTF * INF / 8) / 256, 256>>>(wp, ws, wz);
    gemm_kernel<<<dim3(OUTF / BN, MDIM / BM), 256, SMEM_BYTES>>>(out);
}

// round 4
// speedup vs baseline: 1.1337x; 1.1337x over previous
#include <cuda_runtime.h>
#include <cuda_fp16.h>
#include <cstdint>

#define OUTF 4096
#define INF  4096
#define MDIM 1024

// fp16 scratch — static device globals (allocation-free)
__device__ __half g_wh[(size_t)OUTF * INF];   // dequantized W [out, in]
__device__ __half g_xh[(size_t)MDIM * INF];   // x fp16 [m, k]

// ---------------------------------------------------------------------------
// helpers
// ---------------------------------------------------------------------------
__device__ __forceinline__ uint32_t smem_u32(const void* p) {
    uint32_t a;
    asm("{ .reg .u64 t; cvta.to.shared.u64 t, %1; cvt.u32.u64 %0, t; }"
        : "=r"(a) : "l"(p));
    return a;
}

__device__ __forceinline__ void cp16(uint32_t saddr, const void* gaddr) {
    asm volatile("cp.async.cg.shared.global [%0], [%1], 16;"
                 :: "r"(saddr), "l"(gaddr) : "memory");
}

// ---------------------------------------------------------------------------
// Kernel 1: fused prep — blocks [0,4096): x fp32->fp16 ; [4096,12288): dequant
// ---------------------------------------------------------------------------
__global__ void prep_kernel(const float4* __restrict__ x,
                            const int* __restrict__ wp,
                            const float* __restrict__ ws,
                            const int* __restrict__ wz) {
    int b = blockIdx.x;
    int t = threadIdx.x;
    if (b < 4096) {
        int i = b * 256 + t;              // one float4 per thread
        float4 v = x[i];
        __half2 a = __floats2half2_rn(v.x, v.y);
        __half2 c = __floats2half2_rn(v.z, v.w);
        uint2 u;
        u.x = *reinterpret_cast<uint32_t*>(&a);
        u.y = *reinterpret_cast<uint32_t*>(&c);
        reinterpret_cast<uint2*>(g_xh)[i] = u;
    } else {
        int p = (b - 4096) * 256 + t;     // one packed int32 per thread
        int v = wp[p];
        int o    = p >> 9;                // 512 packed ints per output row
        int col8 = p & 511;
        int g    = col8 >> 4;             // group index
        float s = ws[o * 32 + g];
        float z = (float)wz[o * 32 + g];
        uint32_t pk[4];
#pragma unroll
        for (int jj = 0; jj < 4; ++jj) {
            int q0 = (v >> (8 * jj)) & 15;
            int q1 = (v >> (8 * jj + 4)) & 15;
            q0 = (q0 ^ 8) - 8;            // signed 4-bit
            q1 = (q1 ^ 8) - 8;
            __half2 h = __floats2half2_rn(((float)q0 - z) * s, ((float)q1 - z) * s);
            pk[jj] = *reinterpret_cast<uint32_t*>(&h);
        }
        *reinterpret_cast<uint4*>(&g_wh[(size_t)o * INF + col8 * 8]) =
            make_uint4(pk[0], pk[1], pk[2], pk[3]);
    }
}

// ---------------------------------------------------------------------------
// Kernel 2: mma.sync fp16 GEMM — CTA 128x256, BK=64 halves, 4-stage cp.async
// 8 warps as 2(M) x 4(N); warp tile 64x64; mma.m16n8k16, fp32 accum.
// ---------------------------------------------------------------------------
constexpr int BM = 128, BN = 256, BK = 64;
constexpr int STAGES = 4;
constexpr int NIT = INF / BK;                 // 64
constexpr int TILE_A = BM * 128;              // 16384 B
constexpr int TILE_B = BN * 128;              // 32768 B
constexpr int STG = TILE_A + TILE_B;          // 49152 B
constexpr int SMEM_BYTES = STAGES * STG;      // 196608 B

__global__ void __launch_bounds__(256, 1) gemm_kernel(float* __restrict__ out) {
    extern __shared__ char smem[];
    const uint32_t sb = smem_u32(smem);
    const int tid = threadIdx.x;
    const int wid = tid >> 5;
    const int lid = tid & 31;
    const int wm = wid >> 2;                  // 0..1  (64 M-rows each)
    const int wn = wid & 3;                   // 0..3  (64 N-rows each)
    const int n0 = blockIdx.x * BN;
    const int m0 = blockIdx.y * BM;

    const char* gA = (const char*)g_xh + (size_t)m0 * (INF * 2);
    const char* gB = (const char*)g_wh + (size_t)n0 * (INF * 2);

    // cp.async pattern: A = 1024 16B-chunks (4/thread), B = 2048 (8/thread)
    uint32_t soffA[4]; size_t goffA[4];
#pragma unroll
    for (int r = 0; r < 4; ++r) {
        int idx = tid + r * 256;
        int row = idx >> 3;
        int cc  = idx & 7;
        soffA[r] = (uint32_t)(row * 128 + ((cc ^ (row & 7)) << 4));
        goffA[r] = (size_t)row * (INF * 2) + (size_t)cc * 16;
    }
    uint32_t soffB[8]; size_t goffB[8];
#pragma unroll
    for (int r = 0; r < 8; ++r) {
        int idx = tid + r * 256;
        int row = idx >> 3;
        int cc  = idx & 7;
        soffB[r] = (uint32_t)(row * 128 + ((cc ^ (row & 7)) << 4));
        goffB[r] = (size_t)row * (INF * 2) + (size_t)cc * 16;
    }
    auto load_chunk = [&](int kc, int s) {
        uint32_t tb = sb + s * STG;
        size_t kb = (size_t)kc * 128;
#pragma unroll
        for (int r = 0; r < 4; ++r) cp16(tb + soffA[r], gA + goffA[r] + kb);
#pragma unroll
        for (int r = 0; r < 8; ++r) cp16(tb + TILE_A + soffB[r], gB + goffB[r] + kb);
        asm volatile("cp.async.commit_group;" ::: "memory");
    };

    // ldmatrix addressing (same mapping that passed in R3)
    const int a_row7 = wm * 64 + (lid & 15);       // + i*16
    const int a_cb   = lid >> 4;                   // 16B chunk within k64
    const int b_lrow = (lid & 7) + ((lid >> 4) << 3);
    const int b_cb   = (lid >> 3) & 1;
    const int b_row0 = wn * 64 + b_lrow;           // + h*16

    float acc[4][8][4];
#pragma unroll
    for (int i = 0; i < 4; ++i)
#pragma unroll
        for (int j = 0; j < 8; ++j)
#pragma unroll
            for (int q = 0; q < 4; ++q) acc[i][j][q] = 0.f;

    load_chunk(0, 0);
    load_chunk(1, 1);
    load_chunk(2, 2);
    asm volatile("cp.async.wait_group 2;" ::: "memory");
    __syncthreads();

    for (int it = 0; it < NIT; ++it) {
        const uint32_t tb = sb + (it & 3) * STG;
#pragma unroll
        for (int ks = 0; ks < 4; ++ks) {           // 4 x k16 per 64-half chunk
            uint32_t a[4][4];
#pragma unroll
            for (int i = 0; i < 4; ++i) {
                int row = a_row7 + i * 16;
                uint32_t ad = tb + row * 128
                            + ((((ks << 1) + a_cb) ^ (row & 7)) << 4);
                asm volatile(
                    "ldmatrix.sync.aligned.m8n8.x4.shared.b16 {%0,%1,%2,%3}, [%4];"
                    : "=r"(a[i][0]), "=r"(a[i][1]), "=r"(a[i][2]), "=r"(a[i][3])
                    : "r"(ad));
            }
            uint32_t bfr[8][2];
#pragma unroll
            for (int h = 0; h < 4; ++h) {
                int row = b_row0 + h * 16;
                uint32_t bd = tb + TILE_A + row * 128
                            + ((((ks << 1) + b_cb) ^ (row & 7)) << 4);
                uint32_t r0, r1, r2, r3;
                asm volatile(
                    "ldmatrix.sync.aligned.m8n8.x4.shared.b16 {%0,%1,%2,%3}, [%4];"
                    : "=r"(r0), "=r"(r1), "=r"(r2), "=r"(r3) : "r"(bd));
                bfr[2 * h][0] = r0;     bfr[2 * h][1] = r1;
                bfr[2 * h + 1][0] = r2; bfr[2 * h + 1][1] = r3;
            }
#pragma unroll
            for (int i = 0; i < 4; ++i)
#pragma unroll
                for (int j = 0; j < 8; ++j)
                    asm volatile(
                        "mma.sync.aligned.m16n8k16.row.col.f32.f16.f16.f32 "
                        "{%0,%1,%2,%3},{%4,%5,%6,%7},{%8,%9},{%0,%1,%2,%3};"
                        : "+f"(acc[i][j][0]), "+f"(acc[i][j][1]),
                          "+f"(acc[i][j][2]), "+f"(acc[i][j][3])
                        : "r"(a[i][0]), "r"(a[i][1]), "r"(a[i][2]), "r"(a[i][3]),
                          "r"(bfr[j][0]), "r"(bfr[j][1]));
        }
        if (it + 3 < NIT) {
            load_chunk(it + 3, (it + 3) & 3);
            asm volatile("cp.async.wait_group 3;" ::: "memory");
        } else {
            asm volatile("cp.async.wait_group 0;" ::: "memory");
        }
        __syncthreads();
    }

    // epilogue
    const int mrow = m0 + wm * 64 + (lid >> 2);
    const int ncol = n0 + wn * 64 + ((lid & 3) << 1);
#pragma unroll
    for (int i = 0; i < 4; ++i) {
#pragma unroll
        for (int j = 0; j < 8; ++j) {
            float* p0 = out + (size_t)(mrow + i * 16) * OUTF + ncol + j * 8;
            float* p1 = out + (size_t)(mrow + i * 16 + 8) * OUTF + ncol + j * 8;
            *reinterpret_cast<float2*>(p0) = make_float2(acc[i][j][0], acc[i][j][1]);
            *reinterpret_cast<float2*>(p1) = make_float2(acc[i][j][2], acc[i][j][3]);
        }
    }
}

// ---------------------------------------------------------------------------
// launch
// ---------------------------------------------------------------------------
extern "C" void kernel_launch(void* const* d_in, const int* in_sizes, int n_in,
                              void* d_out, int out_size) {
    const float* x  = (const float*)d_in[0];
    const int*   wp = (const int*)d_in[1];
    const float* ws = (const float*)d_in[2];
    const int*   wz = (const int*)d_in[3];
    float* out = (float*)d_out;

    cudaFuncSetAttribute(gemm_kernel,
                         cudaFuncAttributeMaxDynamicSharedMemorySize, SMEM_BYTES);

    prep_kernel<<<4096 + 8192, 256>>>(reinterpret_cast<const float4*>(x),
                                      wp, ws, wz);
    gemm_kernel<<<dim3(OUTF / BN, MDIM / BM), 256, SMEM_BYTES>>>(out);
}